// round 13
// baseline (speedup 1.0000x reference)
#include <cuda_runtime.h>
#include <cuda_fp16.h>

typedef unsigned long long ull;

#define NN 50000
#define IN_CH 128
#define OUT_CH 64
#define HEADS 4
#define HC 256            // HEADS*OUT_CH
#define MAX_E 800000
#define MAX_TE (MAX_E + NN)
#define NEG_SLOPE 0.2f
#define MAX_RT ((NN + 15) / 16)   // 3125 row tiles

// ---------------- scratch (allocation-free) ----------------
__device__ float  g_h[(size_t)NN * HC];            // 51.2 MB (fp32 h)
__device__ uint4  g_Ahi[(size_t)MAX_RT * 8 * 32];  // 12.8 MB packed A frags (fp16 hi)
__device__ uint4  g_Alo[(size_t)MAX_RT * 8 * 32];  // 12.8 MB packed A frags (fp16 lo)
__device__ ull    g_B16[8 * 32 * 32];              // 64 KB packed B frags (fp16)
__device__ float  g_asrc[NN * HEADS];
__device__ float  g_adst[NN * HEADS];
__device__ int    g_cnt[NN];
__device__ int    g_rowstart[NN + 1];
__device__ int    g_cursor[NN];
__device__ int    g_blocksums[128];
__device__ int    g_col[MAX_TE];

// ---------------- helpers ----------------
__device__ __forceinline__ float lrelu(float v) {
    return v >= 0.f ? v : NEG_SLOPE * v;
}
__device__ __forceinline__ int clampN(int v, int N) {
    v = v < 0 ? 0 : v;
    return v >= N ? N - 1 : v;
}
__device__ __forceinline__ unsigned pack_h2_hi(float a, float b,
                                               float& ra, float& rb) {
    __half ha = __float2half_rn(a);
    __half hb = __float2half_rn(b);
    ra = a - __half2float(ha);
    rb = b - __half2float(hb);
    __half2 p = {ha, hb};
    return *(unsigned*)&p;
}
__device__ __forceinline__ unsigned pack_h2(float a, float b) {
    __half2 p = {__float2half_rn(a), __float2half_rn(b)};
    return *(unsigned*)&p;
}
__device__ __forceinline__ void mma_f16(float* d, const uint4& a,
                                        unsigned b0, unsigned b1) {
    asm("mma.sync.aligned.m16n8k16.row.col.f32.f16.f16.f32 "
        "{%0,%1,%2,%3}, {%4,%5,%6,%7}, {%8,%9}, {%0,%1,%2,%3};"
        : "+f"(d[0]), "+f"(d[1]), "+f"(d[2]), "+f"(d[3])
        : "r"(a.x), "r"(a.y), "r"(a.z), "r"(a.w), "r"(b0), "r"(b1));
}
__device__ __forceinline__ ull splat2(float x) {
    ull r;
    asm("mov.b64 %0, {%1, %1};" : "=l"(r) : "r"(__float_as_uint(x)));
    return r;
}
__device__ __forceinline__ void fma2(ull& d, ull a, ull b) {
    asm("fma.rn.f32x2 %0, %1, %2, %0;" : "+l"(d) : "l"(a), "l"(b));
}
__device__ __forceinline__ float2 unpk(ull v) {
    float2 f;
    f.x = __uint_as_float((unsigned)v);
    f.y = __uint_as_float((unsigned)(v >> 32));
    return f;
}

// ---------------- K1a: split x into packed fp16 A fragments (hi/lo) ----------------
__global__ void k_split_x(const float* __restrict__ x, int N, int RTn) {
    int idx = blockIdx.x * blockDim.x + threadIdx.x;
    if (idx >= RTn * 8 * 32) return;
    int t  = idx & 31;
    int q  = (idx >> 5) & 7;
    int rt = idx >> 8;
    int r0 = rt * 16 + (t >> 2);
    int r1 = r0 + 8;
    int r0c = r0 < N ? r0 : N - 1;
    int r1c = r1 < N ? r1 : N - 1;
    int c0 = q * 16 + (t & 3) * 2;
    float2 p0 = *(const float2*)&x[(size_t)r0c * IN_CH + c0];       // a0
    float2 p1 = *(const float2*)&x[(size_t)r1c * IN_CH + c0];       // a1
    float2 p2 = *(const float2*)&x[(size_t)r0c * IN_CH + c0 + 8];   // a2
    float2 p3 = *(const float2*)&x[(size_t)r1c * IN_CH + c0 + 8];   // a3
    float l0a, l0b, l1a, l1b, l2a, l2b, l3a, l3b;
    uint4 hi, lo;
    hi.x = pack_h2_hi(p0.x, p0.y, l0a, l0b);
    hi.y = pack_h2_hi(p1.x, p1.y, l1a, l1b);
    hi.z = pack_h2_hi(p2.x, p2.y, l2a, l2b);
    hi.w = pack_h2_hi(p3.x, p3.y, l3a, l3b);
    lo.x = pack_h2(l0a, l0b);
    lo.y = pack_h2(l1a, l1b);
    lo.z = pack_h2(l2a, l2b);
    lo.w = pack_h2(l3a, l3b);
    g_Ahi[idx] = hi;
    g_Alo[idx] = lo;
}

// ---------------- K1b: W -> packed fp16 B fragments + zero cnt ----------------
__global__ void k_split_w(const float* __restrict__ W, int N) {
    int idx = blockIdx.x * blockDim.x + threadIdx.x;
    if (idx < N) g_cnt[idx] = 0;
    if (idx >= 8 * 32 * 32) return;
    int t  = idx & 31;
    int nt = (idx >> 5) & 31;
    int q  = idx >> 10;
    int n  = nt * 8 + (t >> 2);
    int k0 = q * 16 + (t & 3) * 2;
    float v0 = __ldg(&W[(k0 + 0) * HC + n]);
    float v1 = __ldg(&W[(k0 + 1) * HC + n]);
    float v2 = __ldg(&W[(k0 + 8) * HC + n]);
    float v3 = __ldg(&W[(k0 + 9) * HC + n]);
    unsigned b0 = pack_h2(v0, v1);
    unsigned b1 = pack_h2(v2, v3);
    g_B16[idx] = (ull)b0 | ((ull)b1 << 32);
}

// ---------------- K1c: h = x @ W via 2-MMA fp16 split, fp32 store ----------------
// block: 8 warps, 2 row tiles; warp w: rt = rt0 + (w>>2), quarter = w&3 (64 cols)
__global__ __launch_bounds__(256) void k_mma(int N, int RTn) {
    __shared__ uint4 sAh[2][8][32];   // 8 KB
    __shared__ uint4 sAl[2][8][32];   // 8 KB
    const int tid = threadIdx.x;
    const int wid = tid >> 5;
    const int t   = tid & 31;
    const int rt0 = blockIdx.x * 2;

#pragma unroll
    for (int it = 0; it < 2; it++) {
        int e = tid + it * 256;                 // 0..511
        int rtl = e >> 8;
        int q   = (e >> 5) & 7;
        int tt  = e & 31;
        int rtg = rt0 + rtl;
        if (rtg >= RTn) rtg = RTn - 1;
        size_t gidx = ((size_t)rtg * 8 + q) * 32 + tt;
        sAh[rtl][q][tt] = g_Ahi[gidx];
        sAl[rtl][q][tt] = g_Alo[gidx];
    }
    __syncthreads();

    const int rtl = wid >> 2;
    const int rt  = rt0 + rtl;
    if (rt >= RTn) return;
    const int quarter = wid & 3;

    float acc[8][4];
#pragma unroll
    for (int nt = 0; nt < 8; nt++)
#pragma unroll
        for (int j = 0; j < 4; j++) acc[nt][j] = 0.f;

#pragma unroll
    for (int q = 0; q < 8; q++) {
        uint4 ah = sAh[rtl][q][t];
        uint4 al = sAl[rtl][q][t];
        const ull* bp = &g_B16[((q * 32) + quarter * 8) * 32 + t];
#pragma unroll
        for (int nt = 0; nt < 8; nt++) {
            ull bv = __ldg(bp + nt * 32);
            unsigned b0 = (unsigned)bv, b1 = (unsigned)(bv >> 32);
            mma_f16(acc[nt], ah, b0, b1);   // hi * W
            mma_f16(acc[nt], al, b0, b1);   // lo * W
        }
    }

    int r0 = rt * 16 + (t >> 2);
    int r1 = r0 + 8;
    int ncol0 = quarter * 64 + (t & 3) * 2;
#pragma unroll
    for (int nt = 0; nt < 8; nt++) {
        int n0 = ncol0 + nt * 8;
        if (r0 < N)
            *(float2*)&g_h[(size_t)r0 * HC + n0] = make_float2(acc[nt][0], acc[nt][1]);
        if (r1 < N)
            *(float2*)&g_h[(size_t)r1 * HC + n0] = make_float2(acc[nt][2], acc[nt][3]);
    }
}

// ---------------- K2: per-node attention logits (fp32 h) ----------------
__global__ void k_logits(const float* __restrict__ att_src,
                         const float* __restrict__ att_dst, int N) {
    int t = blockIdx.x * blockDim.x + threadIdx.x;
    if (t >= N * HEADS) return;
    int n = t >> 2, hh = t & 3;
    const float4* hv = (const float4*)(g_h + (size_t)n * HC + hh * OUT_CH);
    const float4* as = (const float4*)(att_src + hh * OUT_CH);
    const float4* ad = (const float4*)(att_dst + hh * OUT_CH);
    float s = 0.f, d = 0.f;
#pragma unroll
    for (int c = 0; c < 16; c++) {
        float4 h4 = hv[c];
        float4 a4 = __ldg(&as[c]);
        float4 b4 = __ldg(&ad[c]);
        s += h4.x * a4.x + h4.y * a4.y + h4.z * a4.z + h4.w * a4.w;
        d += h4.x * b4.x + h4.y * b4.y + h4.z * b4.z + h4.w * b4.w;
    }
    g_asrc[t] = s;
    g_adst[t] = d;
}

// ---------------- K3: in-degree histogram over dst (2 edges/thread) ----------------
__global__ void k_hist(const int* __restrict__ ei, int E, int N) {
    int t = blockIdx.x * blockDim.x + threadIdx.x;
    int e = t * 2;
    if (e + 1 < E) {
        int2 d2 = __ldg((const int2*)(ei + E + e));
        atomicAdd(&g_cnt[clampN(d2.x, N)], 1);
        atomicAdd(&g_cnt[clampN(d2.y, N)], 1);
    } else if (e < E) {
        atomicAdd(&g_cnt[clampN(__ldg(ei + E + e), N)], 1);
    }
}

// ---------------- K4a/b/c: exclusive scan (+ self-loop slots) ----------------
__global__ void k_scan1(int n) {
    __shared__ int sh[512];
    int i = blockIdx.x * 512 + threadIdx.x;
    sh[threadIdx.x] = (i < n) ? g_cnt[i] : 0;
    __syncthreads();
    for (int off = 256; off > 0; off >>= 1) {
        if (threadIdx.x < off) sh[threadIdx.x] += sh[threadIdx.x + off];
        __syncthreads();
    }
    if (threadIdx.x == 0) g_blocksums[blockIdx.x] = sh[0];
}

__global__ void k_scan2(int nb) {
    __shared__ int sh[128];
    int t = threadIdx.x;
    int v = (t < nb) ? g_blocksums[t] : 0;
    sh[t] = v;
    __syncthreads();
    for (int off = 1; off < 128; off <<= 1) {
        int tmp = (t >= off) ? sh[t - off] : 0;
        __syncthreads();
        sh[t] += tmp;
        __syncthreads();
    }
    if (t < nb) g_blocksums[t] = sh[t] - v;    // exclusive
}

__global__ void k_scan3(int n) {               // +i adds self-loop slots
    __shared__ int sh[512];
    int i = blockIdx.x * 512 + threadIdx.x;
    int v = (i < n) ? g_cnt[i] : 0;
    sh[threadIdx.x] = v;
    __syncthreads();
    for (int off = 1; off < 512; off <<= 1) {
        int tmp = (threadIdx.x >= off) ? sh[threadIdx.x - off] : 0;
        __syncthreads();
        sh[threadIdx.x] += tmp;
        __syncthreads();
    }
    int excl = sh[threadIdx.x] - v + g_blocksums[blockIdx.x] + i;
    if (i < n) { g_rowstart[i] = excl; g_cursor[i] = excl; }
    if (i == n - 1) g_rowstart[n] = excl + v + 1;
}

// ---------------- K5: fill CSR columns (4 edges/thread + self-loops) ----------------
__global__ void k_fill(const int* __restrict__ ei, int E, int TE, int N) {
    int t = blockIdx.x * blockDim.x + threadIdx.x;
    int e = t * 4;
    if (e + 3 < E) {
        int4 s4 = __ldg((const int4*)(ei + e));
        int4 d4 = __ldg((const int4*)(ei + E + e));
        g_col[atomicAdd(&g_cursor[clampN(d4.x, N)], 1)] = clampN(s4.x, N);
        g_col[atomicAdd(&g_cursor[clampN(d4.y, N)], 1)] = clampN(s4.y, N);
        g_col[atomicAdd(&g_cursor[clampN(d4.z, N)], 1)] = clampN(s4.z, N);
        g_col[atomicAdd(&g_cursor[clampN(d4.w, N)], 1)] = clampN(s4.w, N);
    } else {
        for (; e < E; e++) {
            int s = clampN(__ldg(ei + e), N);
            int d = clampN(__ldg(ei + E + e), N);
            g_col[atomicAdd(&g_cursor[d], 1)] = s;
        }
    }
    if (t < N) g_col[atomicAdd(&g_cursor[t], 1)] = t;   // self-loops
}

// ---------------- K6: single-pass gather-aggregate (fp32, FFMA2) ----------------
// acc = sum exp(e)*h, den = sum exp(e); normalize once at the end.
__global__ __launch_bounds__(256) void k_aggregate(const float* __restrict__ bias,
                                                   float* __restrict__ out, int N) {
    int warp = (int)((blockIdx.x * (unsigned)blockDim.x + threadIdx.x) >> 5);
    if (warp >= N) return;
    int lane = threadIdx.x & 31;
    int head = lane >> 3;

    int start = g_rowstart[warp];
    int end   = g_rowstart[warp + 1];
    float adst_h = __ldg(&g_adst[(size_t)warp * 4 + head]);

    float den = 0.f;
    ull acc[4];
#pragma unroll
    for (int j = 0; j < 4; j++) acc[j] = 0ull;
    const int cbase = lane * 8;

    int i = start;
    for (; i + 1 < end; i += 2) {
        int s0 = __ldg(&g_col[i]);
        int s1 = __ldg(&g_col[i + 1]);
        const ulonglong2* hp0 = (const ulonglong2*)(g_h + (size_t)s0 * HC + cbase);
        const ulonglong2* hp1 = (const ulonglong2*)(g_h + (size_t)s1 * HC + cbase);
        ulonglong2 p0a = hp0[0], p0b = hp0[1];
        ulonglong2 p1a = hp1[0], p1b = hp1[1];
        float a0 = __ldg(&g_asrc[(size_t)s0 * 4 + head]);
        float a1 = __ldg(&g_asrc[(size_t)s1 * 4 + head]);
        float w0 = __expf(lrelu(a0 + adst_h));
        float w1 = __expf(lrelu(a1 + adst_h));
        den += w0 + w1;
        ull ww0 = splat2(w0), ww1 = splat2(w1);
        fma2(acc[0], ww0, p0a.x);
        fma2(acc[1], ww0, p0a.y);
        fma2(acc[2], ww0, p0b.x);
        fma2(acc[3], ww0, p0b.y);
        fma2(acc[0], ww1, p1a.x);
        fma2(acc[1], ww1, p1a.y);
        fma2(acc[2], ww1, p1b.x);
        fma2(acc[3], ww1, p1b.y);
    }
    if (i < end) {
        int s0 = __ldg(&g_col[i]);
        const ulonglong2* hp0 = (const ulonglong2*)(g_h + (size_t)s0 * HC + cbase);
        ulonglong2 p0a = hp0[0], p0b = hp0[1];
        float a0 = __ldg(&g_asrc[(size_t)s0 * 4 + head]);
        float w0 = __expf(lrelu(a0 + adst_h));
        den += w0;
        ull ww0 = splat2(w0);
        fma2(acc[0], ww0, p0a.x);
        fma2(acc[1], ww0, p0a.y);
        fma2(acc[2], ww0, p0b.x);
        fma2(acc[3], ww0, p0b.y);
    }

    float inv_den = 1.0f / (den + 1e-16f);
    float2 c0 = unpk(acc[0]), c1 = unpk(acc[1]);
    float2 c2 = unpk(acc[2]), c3 = unpk(acc[3]);
    const float4* bp = (const float4*)(bias + cbase);
    float4 b0 = __ldg(bp), b1 = __ldg(bp + 1);
    float4 o0 = {c0.x * inv_den + b0.x, c0.y * inv_den + b0.y,
                 c1.x * inv_den + b0.z, c1.y * inv_den + b0.w};
    float4 o1 = {c2.x * inv_den + b1.x, c2.y * inv_den + b1.y,
                 c3.x * inv_den + b1.z, c3.y * inv_den + b1.w};
    float4* op = (float4*)(out + (size_t)warp * HC + cbase);
    op[0] = o0;
    op[1] = o1;
}

// ---------------- launch ----------------
extern "C" void kernel_launch(void* const* d_in, const int* in_sizes, int n_in,
                              void* d_out, int out_size) {
    const float* x       = (const float*)d_in[0];
    const int*   ei      = (const int*)d_in[1];     // int32
    const float* W       = (const float*)d_in[2];
    const float* att_src = (const float*)d_in[3];
    const float* att_dst = (const float*)d_in[4];
    const float* bias    = (const float*)d_in[5];
    float*       out     = (float*)d_out;

    const int N   = in_sizes[0] / IN_CH;   // 50000
    const int E   = in_sizes[1] / 2;       // 800000
    const int TE  = E + N;                 // 850000
    const int NH  = N * HEADS;
    const int RTn = (N + 15) / 16;         // 3125
    const int NB512 = (N + 511) / 512;     // 98
    const int E4 = (E + 3) / 4;
    const int E2 = (E + 1) / 2;

    k_split_x<<<(RTn * 256 + 255) / 256, 256>>>(x, N, RTn);
    k_split_w<<<(N + 255) / 256, 256>>>(W, N);   // also zeroes g_cnt
    k_mma<<<(RTn + 1) / 2, 256>>>(N, RTn);
    k_logits<<<(NH + 255) / 256, 256>>>(att_src, att_dst, N);
    k_hist<<<(E2 + 255) / 256, 256>>>(ei, E, N);
    k_scan1<<<NB512, 512>>>(N);
    k_scan2<<<1, 128>>>(NB512);
    k_scan3<<<NB512, 512>>>(N);
    int fill_threads = (E4 > N ? E4 : N);
    k_fill<<<(fill_threads + 255) / 256, 256>>>(ei, E, TE, N);
    long long agg_threads = (long long)N * 32;
    k_aggregate<<<(unsigned)((agg_threads + 255) / 256), 256>>>(bias, out, N);
}

// round 15
// speedup vs baseline: 1.1814x; 1.1814x over previous
#include <cuda_runtime.h>
#include <cuda_fp16.h>

typedef unsigned long long ull;

#define NN 50000
#define IN_CH 128
#define OUT_CH 64
#define HEADS 4
#define HC 256            // HEADS*OUT_CH
#define MAX_E 800000
#define MAX_TE (MAX_E + NN)
#define NEG_SLOPE 0.2f
#define MAX_RT ((NN + 15) / 16)   // 3125 row tiles

// ---------------- scratch (allocation-free) ----------------
__device__ __half g_h16[(size_t)NN * HC];          // 25.6 MB (fp16 h, L2-resident)
__device__ uint4  g_Ahi[(size_t)MAX_RT * 8 * 32];  // 12.8 MB packed A frags (fp16 hi)
__device__ uint4  g_Alo[(size_t)MAX_RT * 8 * 32];  // 12.8 MB packed A frags (fp16 lo)
__device__ ull    g_B16[8 * 32 * 32];              // 64 KB packed B frags (fp16)
__device__ float  g_asrc[NN * HEADS];
__device__ float  g_adst[NN * HEADS];
__device__ int    g_cnt[NN];
__device__ int    g_rowstart[NN + 1];
__device__ int    g_cursor[NN];
__device__ int    g_blocksums[128];
__device__ int    g_col[MAX_TE];

// ---------------- helpers ----------------
__device__ __forceinline__ float lrelu(float v) {
    return v >= 0.f ? v : NEG_SLOPE * v;
}
__device__ __forceinline__ int clampN(int v, int N) {
    v = v < 0 ? 0 : v;
    return v >= N ? N - 1 : v;
}
__device__ __forceinline__ unsigned pack_h2_hi(float a, float b,
                                               float& ra, float& rb) {
    __half ha = __float2half_rn(a);
    __half hb = __float2half_rn(b);
    ra = a - __half2float(ha);
    rb = b - __half2float(hb);
    __half2 p = {ha, hb};
    return *(unsigned*)&p;
}
__device__ __forceinline__ unsigned pack_h2(float a, float b) {
    __half2 p = {__float2half_rn(a), __float2half_rn(b)};
    return *(unsigned*)&p;
}
__device__ __forceinline__ void mma_f16(float* d, const uint4& a,
                                        unsigned b0, unsigned b1) {
    asm("mma.sync.aligned.m16n8k16.row.col.f32.f16.f16.f32 "
        "{%0,%1,%2,%3}, {%4,%5,%6,%7}, {%8,%9}, {%0,%1,%2,%3};"
        : "+f"(d[0]), "+f"(d[1]), "+f"(d[2]), "+f"(d[3])
        : "r"(a.x), "r"(a.y), "r"(a.z), "r"(a.w), "r"(b0), "r"(b1));
}

// ---------------- K1a: split x into packed fp16 A fragments (hi/lo) ----------------
__global__ void k_split_x(const float* __restrict__ x, int N, int RTn) {
    int idx = blockIdx.x * blockDim.x + threadIdx.x;
    if (idx >= RTn * 8 * 32) return;
    int t  = idx & 31;
    int q  = (idx >> 5) & 7;
    int rt = idx >> 8;
    int r0 = rt * 16 + (t >> 2);
    int r1 = r0 + 8;
    int r0c = r0 < N ? r0 : N - 1;
    int r1c = r1 < N ? r1 : N - 1;
    int c0 = q * 16 + (t & 3) * 2;
    float2 p0 = *(const float2*)&x[(size_t)r0c * IN_CH + c0];       // a0
    float2 p1 = *(const float2*)&x[(size_t)r1c * IN_CH + c0];       // a1
    float2 p2 = *(const float2*)&x[(size_t)r0c * IN_CH + c0 + 8];   // a2
    float2 p3 = *(const float2*)&x[(size_t)r1c * IN_CH + c0 + 8];   // a3
    float l0a, l0b, l1a, l1b, l2a, l2b, l3a, l3b;
    uint4 hi, lo;
    hi.x = pack_h2_hi(p0.x, p0.y, l0a, l0b);
    hi.y = pack_h2_hi(p1.x, p1.y, l1a, l1b);
    hi.z = pack_h2_hi(p2.x, p2.y, l2a, l2b);
    hi.w = pack_h2_hi(p3.x, p3.y, l3a, l3b);
    lo.x = pack_h2(l0a, l0b);
    lo.y = pack_h2(l1a, l1b);
    lo.z = pack_h2(l2a, l2b);
    lo.w = pack_h2(l3a, l3b);
    g_Ahi[idx] = hi;
    g_Alo[idx] = lo;
}

// ---------------- K1b: W -> packed fp16 B fragments + zero cnt ----------------
__global__ void k_split_w(const float* __restrict__ W, int N) {
    int idx = blockIdx.x * blockDim.x + threadIdx.x;
    if (idx < N) g_cnt[idx] = 0;
    if (idx >= 8 * 32 * 32) return;
    int t  = idx & 31;
    int nt = (idx >> 5) & 31;
    int q  = idx >> 10;
    int n  = nt * 8 + (t >> 2);
    int k0 = q * 16 + (t & 3) * 2;
    float v0 = __ldg(&W[(k0 + 0) * HC + n]);
    float v1 = __ldg(&W[(k0 + 1) * HC + n]);
    float v2 = __ldg(&W[(k0 + 8) * HC + n]);
    float v3 = __ldg(&W[(k0 + 9) * HC + n]);
    unsigned b0 = pack_h2(v0, v1);
    unsigned b1 = pack_h2(v2, v3);
    g_B16[idx] = (ull)b0 | ((ull)b1 << 32);
}

// ---------------- K1c: h = x @ W via 2-MMA fp16 split, smem A staging ----------------
// block: 8 warps, 2 row tiles; warp w: rt = rt0 + (w>>2), quarter = w&3 (64 cols)
__global__ __launch_bounds__(256) void k_mma(int N, int RTn) {
    __shared__ uint4 sAh[2][8][32];   // 8 KB
    __shared__ uint4 sAl[2][8][32];   // 8 KB
    const int tid = threadIdx.x;
    const int wid = tid >> 5;
    const int t   = tid & 31;
    const int rt0 = blockIdx.x * 2;

#pragma unroll
    for (int it = 0; it < 2; it++) {
        int e = tid + it * 256;                 // 0..511
        int rtl = e >> 8;
        int q   = (e >> 5) & 7;
        int tt  = e & 31;
        int rtg = rt0 + rtl;
        if (rtg >= RTn) rtg = RTn - 1;
        size_t gidx = ((size_t)rtg * 8 + q) * 32 + tt;
        sAh[rtl][q][tt] = g_Ahi[gidx];
        sAl[rtl][q][tt] = g_Alo[gidx];
    }
    __syncthreads();

    const int rtl = wid >> 2;
    const int rt  = rt0 + rtl;
    if (rt >= RTn) return;
    const int quarter = wid & 3;

    float acc[8][4];
#pragma unroll
    for (int nt = 0; nt < 8; nt++)
#pragma unroll
        for (int j = 0; j < 4; j++) acc[nt][j] = 0.f;

#pragma unroll
    for (int q = 0; q < 8; q++) {
        uint4 ah = sAh[rtl][q][t];
        uint4 al = sAl[rtl][q][t];
        const ull* bp = &g_B16[((q * 32) + quarter * 8) * 32 + t];
#pragma unroll
        for (int nt = 0; nt < 8; nt++) {
            ull bv = __ldg(bp + nt * 32);
            unsigned b0 = (unsigned)bv, b1 = (unsigned)(bv >> 32);
            mma_f16(acc[nt], ah, b0, b1);   // hi * W
            mma_f16(acc[nt], al, b0, b1);   // lo * W
        }
    }

    int r0 = rt * 16 + (t >> 2);
    int r1 = r0 + 8;
    int ncol0 = quarter * 64 + (t & 3) * 2;
#pragma unroll
    for (int nt = 0; nt < 8; nt++) {
        int n0 = ncol0 + nt * 8;
        if (r0 < N)
            *(__half2*)&g_h16[(size_t)r0 * HC + n0] =
                __floats2half2_rn(acc[nt][0], acc[nt][1]);
        if (r1 < N)
            *(__half2*)&g_h16[(size_t)r1 * HC + n0] =
                __floats2half2_rn(acc[nt][2], acc[nt][3]);
    }
}

// ---------------- K2: per-node attention logits (reads fp16 h) ----------------
__global__ void k_logits(const float* __restrict__ att_src,
                         const float* __restrict__ att_dst, int N) {
    int t = blockIdx.x * blockDim.x + threadIdx.x;
    if (t >= N * HEADS) return;
    int n = t >> 2, hh = t & 3;
    const uint2* hv = (const uint2*)(g_h16 + (size_t)n * HC + hh * OUT_CH);
    const float4* as = (const float4*)(att_src + hh * OUT_CH);
    const float4* ad = (const float4*)(att_dst + hh * OUT_CH);
    float s = 0.f, d = 0.f;
#pragma unroll
    for (int c = 0; c < 16; c++) {
        uint2 u = hv[c];
        float2 f0 = __half22float2(*(__half2*)&u.x);
        float2 f1 = __half22float2(*(__half2*)&u.y);
        float4 a4 = __ldg(&as[c]);
        float4 b4 = __ldg(&ad[c]);
        s += f0.x * a4.x + f0.y * a4.y + f1.x * a4.z + f1.y * a4.w;
        d += f0.x * b4.x + f0.y * b4.y + f1.x * b4.z + f1.y * b4.w;
    }
    g_asrc[t] = s;
    g_adst[t] = d;
}

// ---------------- K3: in-degree histogram over dst (2 edges/thread) ----------------
__global__ void k_hist(const int* __restrict__ ei, int E, int N) {
    int t = blockIdx.x * blockDim.x + threadIdx.x;
    int e = t * 2;
    if (e + 1 < E) {
        int2 d2 = __ldg((const int2*)(ei + E + e));
        atomicAdd(&g_cnt[clampN(d2.x, N)], 1);
        atomicAdd(&g_cnt[clampN(d2.y, N)], 1);
    } else if (e < E) {
        atomicAdd(&g_cnt[clampN(__ldg(ei + E + e), N)], 1);
    }
}

// ---------------- K4a/b/c: exclusive scan (+ self-loop slots) ----------------
__global__ void k_scan1(int n) {
    __shared__ int sh[512];
    int i = blockIdx.x * 512 + threadIdx.x;
    sh[threadIdx.x] = (i < n) ? g_cnt[i] : 0;
    __syncthreads();
    for (int off = 256; off > 0; off >>= 1) {
        if (threadIdx.x < off) sh[threadIdx.x] += sh[threadIdx.x + off];
        __syncthreads();
    }
    if (threadIdx.x == 0) g_blocksums[blockIdx.x] = sh[0];
}

__global__ void k_scan2(int nb) {
    __shared__ int sh[128];
    int t = threadIdx.x;
    int v = (t < nb) ? g_blocksums[t] : 0;
    sh[t] = v;
    __syncthreads();
    for (int off = 1; off < 128; off <<= 1) {
        int tmp = (t >= off) ? sh[t - off] : 0;
        __syncthreads();
        sh[t] += tmp;
        __syncthreads();
    }
    if (t < nb) g_blocksums[t] = sh[t] - v;    // exclusive
}

__global__ void k_scan3(int n) {               // +i adds self-loop slots
    __shared__ int sh[512];
    int i = blockIdx.x * 512 + threadIdx.x;
    int v = (i < n) ? g_cnt[i] : 0;
    sh[threadIdx.x] = v;
    __syncthreads();
    for (int off = 1; off < 512; off <<= 1) {
        int tmp = (threadIdx.x >= off) ? sh[threadIdx.x - off] : 0;
        __syncthreads();
        sh[threadIdx.x] += tmp;
        __syncthreads();
    }
    int excl = sh[threadIdx.x] - v + g_blocksums[blockIdx.x] + i;
    if (i < n) { g_rowstart[i] = excl; g_cursor[i] = excl; }
    if (i == n - 1) g_rowstart[n] = excl + v + 1;
}

// ---------------- K5: fill CSR columns (4 edges/thread + self-loops) ----------------
__global__ void k_fill(const int* __restrict__ ei, int E, int TE, int N) {
    int t = blockIdx.x * blockDim.x + threadIdx.x;
    int e = t * 4;
    if (e + 3 < E) {
        int4 s4 = __ldg((const int4*)(ei + e));
        int4 d4 = __ldg((const int4*)(ei + E + e));
        g_col[atomicAdd(&g_cursor[clampN(d4.x, N)], 1)] = clampN(s4.x, N);
        g_col[atomicAdd(&g_cursor[clampN(d4.y, N)], 1)] = clampN(s4.y, N);
        g_col[atomicAdd(&g_cursor[clampN(d4.z, N)], 1)] = clampN(s4.z, N);
        g_col[atomicAdd(&g_cursor[clampN(d4.w, N)], 1)] = clampN(s4.w, N);
    } else {
        for (; e < E; e++) {
            int s = clampN(__ldg(ei + e), N);
            int d = clampN(__ldg(ei + E + e), N);
            g_col[atomicAdd(&g_cursor[d], 1)] = s;
        }
    }
    if (t < N) g_col[atomicAdd(&g_cursor[t], 1)] = t;   // self-loops
}

// ---------------- K6: single-pass gather-aggregate, 4-edge MLP ----------------
// acc = sum exp(e)*h (fp32), den = sum exp(e); normalize once at the end.
__global__ __launch_bounds__(256) void k_aggregate(const float* __restrict__ bias,
                                                   float* __restrict__ out, int N) {
    int warp = (int)((blockIdx.x * (unsigned)blockDim.x + threadIdx.x) >> 5);
    if (warp >= N) return;
    int lane = threadIdx.x & 31;
    int head = lane >> 3;

    int start = g_rowstart[warp];
    int end   = g_rowstart[warp + 1];
    float adst_h = __ldg(&g_adst[(size_t)warp * 4 + head]);

    float den = 0.f;
    float acc[8];
#pragma unroll
    for (int j = 0; j < 8; j++) acc[j] = 0.f;
    const int cbase = lane * 8;

    int i = start;
    // 4-edge unrolled main loop: batch all loads first (4 independent chains)
    for (; i + 3 < end; i += 4) {
        int s0 = __ldg(&g_col[i]);
        int s1 = __ldg(&g_col[i + 1]);
        int s2 = __ldg(&g_col[i + 2]);
        int s3 = __ldg(&g_col[i + 3]);
        uint4 hv0 = *(const uint4*)(g_h16 + (size_t)s0 * HC + cbase);
        uint4 hv1 = *(const uint4*)(g_h16 + (size_t)s1 * HC + cbase);
        uint4 hv2 = *(const uint4*)(g_h16 + (size_t)s2 * HC + cbase);
        uint4 hv3 = *(const uint4*)(g_h16 + (size_t)s3 * HC + cbase);
        float a0 = __ldg(&g_asrc[(size_t)s0 * 4 + head]);
        float a1 = __ldg(&g_asrc[(size_t)s1 * 4 + head]);
        float a2 = __ldg(&g_asrc[(size_t)s2 * 4 + head]);
        float a3 = __ldg(&g_asrc[(size_t)s3 * 4 + head]);
        float w0 = __expf(lrelu(a0 + adst_h));
        float w1 = __expf(lrelu(a1 + adst_h));
        float w2 = __expf(lrelu(a2 + adst_h));
        float w3 = __expf(lrelu(a3 + adst_h));
        den += (w0 + w1) + (w2 + w3);
        float2 f;
        f = __half22float2(*(__half2*)&hv0.x); acc[0] += w0 * f.x; acc[1] += w0 * f.y;
        f = __half22float2(*(__half2*)&hv0.y); acc[2] += w0 * f.x; acc[3] += w0 * f.y;
        f = __half22float2(*(__half2*)&hv0.z); acc[4] += w0 * f.x; acc[5] += w0 * f.y;
        f = __half22float2(*(__half2*)&hv0.w); acc[6] += w0 * f.x; acc[7] += w0 * f.y;
        f = __half22float2(*(__half2*)&hv1.x); acc[0] += w1 * f.x; acc[1] += w1 * f.y;
        f = __half22float2(*(__half2*)&hv1.y); acc[2] += w1 * f.x; acc[3] += w1 * f.y;
        f = __half22float2(*(__half2*)&hv1.z); acc[4] += w1 * f.x; acc[5] += w1 * f.y;
        f = __half22float2(*(__half2*)&hv1.w); acc[6] += w1 * f.x; acc[7] += w1 * f.y;
        f = __half22float2(*(__half2*)&hv2.x); acc[0] += w2 * f.x; acc[1] += w2 * f.y;
        f = __half22float2(*(__half2*)&hv2.y); acc[2] += w2 * f.x; acc[3] += w2 * f.y;
        f = __half22float2(*(__half2*)&hv2.z); acc[4] += w2 * f.x; acc[5] += w2 * f.y;
        f = __half22float2(*(__half2*)&hv2.w); acc[6] += w2 * f.x; acc[7] += w2 * f.y;
        f = __half22float2(*(__half2*)&hv3.x); acc[0] += w3 * f.x; acc[1] += w3 * f.y;
        f = __half22float2(*(__half2*)&hv3.y); acc[2] += w3 * f.x; acc[3] += w3 * f.y;
        f = __half22float2(*(__half2*)&hv3.z); acc[4] += w3 * f.x; acc[5] += w3 * f.y;
        f = __half22float2(*(__half2*)&hv3.w); acc[6] += w3 * f.x; acc[7] += w3 * f.y;
    }
    for (; i < end; i++) {
        int s0 = __ldg(&g_col[i]);
        uint4 hv0 = *(const uint4*)(g_h16 + (size_t)s0 * HC + cbase);
        float a0 = __ldg(&g_asrc[(size_t)s0 * 4 + head]);
        float w0 = __expf(lrelu(a0 + adst_h));
        den += w0;
        float2 f;
        f = __half22float2(*(__half2*)&hv0.x); acc[0] += w0 * f.x; acc[1] += w0 * f.y;
        f = __half22float2(*(__half2*)&hv0.y); acc[2] += w0 * f.x; acc[3] += w0 * f.y;
        f = __half22float2(*(__half2*)&hv0.z); acc[4] += w0 * f.x; acc[5] += w0 * f.y;
        f = __half22float2(*(__half2*)&hv0.w); acc[6] += w0 * f.x; acc[7] += w0 * f.y;
    }

    float inv_den = 1.0f / (den + 1e-16f);
    const float4* bp = (const float4*)(bias + cbase);
    float4 b0 = __ldg(bp), b1 = __ldg(bp + 1);
    float4 o0 = {acc[0] * inv_den + b0.x, acc[1] * inv_den + b0.y,
                 acc[2] * inv_den + b0.z, acc[3] * inv_den + b0.w};
    float4 o1 = {acc[4] * inv_den + b1.x, acc[5] * inv_den + b1.y,
                 acc[6] * inv_den + b1.z, acc[7] * inv_den + b1.w};
    float4* op = (float4*)(out + (size_t)warp * HC + cbase);
    op[0] = o0;
    op[1] = o1;
}

// ---------------- launch ----------------
extern "C" void kernel_launch(void* const* d_in, const int* in_sizes, int n_in,
                              void* d_out, int out_size) {
    const float* x       = (const float*)d_in[0];
    const int*   ei      = (const int*)d_in[1];     // int32
    const float* W       = (const float*)d_in[2];
    const float* att_src = (const float*)d_in[3];
    const float* att_dst = (const float*)d_in[4];
    const float* bias    = (const float*)d_in[5];
    float*       out     = (float*)d_out;

    const int N   = in_sizes[0] / IN_CH;   // 50000
    const int E   = in_sizes[1] / 2;       // 800000
    const int TE  = E + N;                 // 850000
    const int NH  = N * HEADS;
    const int RTn = (N + 15) / 16;         // 3125
    const int NB512 = (N + 511) / 512;     // 98
    const int E4 = (E + 3) / 4;
    const int E2 = (E + 1) / 2;

    k_split_x<<<(RTn * 256 + 255) / 256, 256>>>(x, N, RTn);
    k_split_w<<<(N + 255) / 256, 256>>>(W, N);   // also zeroes g_cnt
    k_mma<<<(RTn + 1) / 2, 256>>>(N, RTn);
    k_logits<<<(NH + 255) / 256, 256>>>(att_src, att_dst, N);
    k_hist<<<(E2 + 255) / 256, 256>>>(ei, E, N);
    k_scan1<<<NB512, 512>>>(N);
    k_scan2<<<1, 128>>>(NB512);
    k_scan3<<<NB512, 512>>>(N);
    int fill_threads = (E4 > N ? E4 : N);
    k_fill<<<(fill_threads + 255) / 256, 256>>>(ei, E, TE, N);
    long long agg_threads = (long long)N * 32;
    k_aggregate<<<(unsigned)((agg_threads + 255) / 256), 256>>>(bias, out, N);
}

// round 17
// speedup vs baseline: 1.4212x; 1.2030x over previous
#include <cuda_runtime.h>
#include <cuda_fp16.h>

typedef unsigned long long ull;

#define NN 50000
#define IN_CH 128
#define OUT_CH 64
#define HEADS 4
#define HC 256            // HEADS*OUT_CH
#define MAX_E 800000
#define MAX_TE (MAX_E + NN)
#define NEG_SLOPE 0.2f
#define MAX_RT ((NN + 15) / 16)   // 3125 row tiles

// ---------------- scratch (allocation-free) ----------------
__device__ __half g_h16[(size_t)NN * HC];          // 25.6 MB (fp16 h, L2-resident)
__device__ uint4  g_Ahi[(size_t)MAX_RT * 8 * 32];  // 12.8 MB packed A frags (fp16 hi)
__device__ uint4  g_Alo[(size_t)MAX_RT * 8 * 32];  // 12.8 MB packed A frags (fp16 lo)
__device__ ull    g_B16[8 * 32 * 32];              // 64 KB packed B frags (fp16)
__device__ float  g_asrc[NN * HEADS];
__device__ float  g_adst[NN * HEADS];
__device__ int    g_cnt[NN];
__device__ int    g_rowstart[NN + 1];
__device__ int    g_cursor[NN];
__device__ int    g_blocksums[128];
__device__ int    g_col[MAX_TE];

// ---------------- helpers ----------------
__device__ __forceinline__ float lrelu(float v) {
    return v >= 0.f ? v : NEG_SLOPE * v;
}
__device__ __forceinline__ int clampN(int v, int N) {
    v = v < 0 ? 0 : v;
    return v >= N ? N - 1 : v;
}
__device__ __forceinline__ unsigned pack_h2_hi(float a, float b,
                                               float& ra, float& rb) {
    __half ha = __float2half_rn(a);
    __half hb = __float2half_rn(b);
    ra = a - __half2float(ha);
    rb = b - __half2float(hb);
    __half2 p = {ha, hb};
    return *(unsigned*)&p;
}
__device__ __forceinline__ unsigned pack_h2(float a, float b) {
    __half2 p = {__float2half_rn(a), __float2half_rn(b)};
    return *(unsigned*)&p;
}
__device__ __forceinline__ void mma_f16(float* d, const uint4& a,
                                        unsigned b0, unsigned b1) {
    asm("mma.sync.aligned.m16n8k16.row.col.f32.f16.f16.f32 "
        "{%0,%1,%2,%3}, {%4,%5,%6,%7}, {%8,%9}, {%0,%1,%2,%3};"
        : "+f"(d[0]), "+f"(d[1]), "+f"(d[2]), "+f"(d[3])
        : "r"(a.x), "r"(a.y), "r"(a.z), "r"(a.w), "r"(b0), "r"(b1));
}

// ---------------- K1a: split x into packed fp16 A fragments (hi/lo) ----------------
__global__ void k_split_x(const float* __restrict__ x, int N, int RTn) {
    int idx = blockIdx.x * blockDim.x + threadIdx.x;
    if (idx >= RTn * 8 * 32) return;
    int t  = idx & 31;
    int q  = (idx >> 5) & 7;
    int rt = idx >> 8;
    int r0 = rt * 16 + (t >> 2);
    int r1 = r0 + 8;
    int r0c = r0 < N ? r0 : N - 1;
    int r1c = r1 < N ? r1 : N - 1;
    int c0 = q * 16 + (t & 3) * 2;
    float2 p0 = *(const float2*)&x[(size_t)r0c * IN_CH + c0];       // a0
    float2 p1 = *(const float2*)&x[(size_t)r1c * IN_CH + c0];       // a1
    float2 p2 = *(const float2*)&x[(size_t)r0c * IN_CH + c0 + 8];   // a2
    float2 p3 = *(const float2*)&x[(size_t)r1c * IN_CH + c0 + 8];   // a3
    float l0a, l0b, l1a, l1b, l2a, l2b, l3a, l3b;
    uint4 hi, lo;
    hi.x = pack_h2_hi(p0.x, p0.y, l0a, l0b);
    hi.y = pack_h2_hi(p1.x, p1.y, l1a, l1b);
    hi.z = pack_h2_hi(p2.x, p2.y, l2a, l2b);
    hi.w = pack_h2_hi(p3.x, p3.y, l3a, l3b);
    lo.x = pack_h2(l0a, l0b);
    lo.y = pack_h2(l1a, l1b);
    lo.z = pack_h2(l2a, l2b);
    lo.w = pack_h2(l3a, l3b);
    g_Ahi[idx] = hi;
    g_Alo[idx] = lo;
}

// ---------------- K1b: W -> packed fp16 B fragments + zero cnt ----------------
__global__ void k_split_w(const float* __restrict__ W, int N) {
    int idx = blockIdx.x * blockDim.x + threadIdx.x;
    if (idx < N) g_cnt[idx] = 0;
    if (idx >= 8 * 32 * 32) return;
    int t  = idx & 31;
    int nt = (idx >> 5) & 31;
    int q  = idx >> 10;
    int n  = nt * 8 + (t >> 2);
    int k0 = q * 16 + (t & 3) * 2;
    float v0 = __ldg(&W[(k0 + 0) * HC + n]);
    float v1 = __ldg(&W[(k0 + 1) * HC + n]);
    float v2 = __ldg(&W[(k0 + 8) * HC + n]);
    float v3 = __ldg(&W[(k0 + 9) * HC + n]);
    unsigned b0 = pack_h2(v0, v1);
    unsigned b1 = pack_h2(v2, v3);
    g_B16[idx] = (ull)b0 | ((ull)b1 << 32);
}

// ---------------- K1c: h = x @ W via 2-MMA fp16 split + FUSED logits ----------------
// block: 8 warps, 2 row tiles; warp w: rt = rt0 + (w>>2), quarter = w&3.
// quarter == head: warp owns head `quarter` for its 16 rows -> logits reduce
// over just 4 lanes (t&3) with 8 SHFLs, using live fp32 accumulators.
__global__ __launch_bounds__(256) void k_mma(const float* __restrict__ att_src,
                                             const float* __restrict__ att_dst,
                                             int N, int RTn) {
    __shared__ uint4 sAh[2][8][32];   // 8 KB
    __shared__ uint4 sAl[2][8][32];   // 8 KB
    const int tid = threadIdx.x;
    const int wid = tid >> 5;
    const int t   = tid & 31;
    const int rt0 = blockIdx.x * 2;

#pragma unroll
    for (int it = 0; it < 2; it++) {
        int e = tid + it * 256;                 // 0..511
        int rtl = e >> 8;
        int q   = (e >> 5) & 7;
        int tt  = e & 31;
        int rtg = rt0 + rtl;
        if (rtg >= RTn) rtg = RTn - 1;
        size_t gidx = ((size_t)rtg * 8 + q) * 32 + tt;
        sAh[rtl][q][tt] = g_Ahi[gidx];
        sAl[rtl][q][tt] = g_Alo[gidx];
    }
    __syncthreads();

    const int rtl = wid >> 2;
    const int rt  = rt0 + rtl;
    if (rt >= RTn) return;
    const int quarter = wid & 3;                // == head index

    float acc[8][4];
#pragma unroll
    for (int nt = 0; nt < 8; nt++)
#pragma unroll
        for (int j = 0; j < 4; j++) acc[nt][j] = 0.f;

#pragma unroll
    for (int q = 0; q < 8; q++) {
        uint4 ah = sAh[rtl][q][t];
        uint4 al = sAl[rtl][q][t];
        const ull* bp = &g_B16[((q * 32) + quarter * 8) * 32 + t];
#pragma unroll
        for (int nt = 0; nt < 8; nt++) {
            ull bv = __ldg(bp + nt * 32);
            unsigned b0 = (unsigned)bv, b1 = (unsigned)(bv >> 32);
            mma_f16(acc[nt], ah, b0, b1);   // hi * W
            mma_f16(acc[nt], al, b0, b1);   // lo * W
        }
    }

    int r0 = rt * 16 + (t >> 2);
    int r1 = r0 + 8;
    int ncol0 = quarter * 64 + (t & 3) * 2;

    // store h16
#pragma unroll
    for (int nt = 0; nt < 8; nt++) {
        int n0 = ncol0 + nt * 8;
        if (r0 < N)
            *(__half2*)&g_h16[(size_t)r0 * HC + n0] =
                __floats2half2_rn(acc[nt][0], acc[nt][1]);
        if (r1 < N)
            *(__half2*)&g_h16[(size_t)r1 * HC + n0] =
                __floats2half2_rn(acc[nt][2], acc[nt][3]);
    }

    // fused logits: per-lane partial dot over owned cols, 4-lane butterfly
    float ps0 = 0.f, pd0 = 0.f, ps1 = 0.f, pd1 = 0.f;
#pragma unroll
    for (int nt = 0; nt < 8; nt++) {
        int c = quarter * OUT_CH + (t & 3) * 2 + nt * 8;   // global att index
        float as_a = __ldg(&att_src[c]);
        float as_b = __ldg(&att_src[c + 1]);
        float ad_a = __ldg(&att_dst[c]);
        float ad_b = __ldg(&att_dst[c + 1]);
        ps0 += acc[nt][0] * as_a + acc[nt][1] * as_b;
        pd0 += acc[nt][0] * ad_a + acc[nt][1] * ad_b;
        ps1 += acc[nt][2] * as_a + acc[nt][3] * as_b;
        pd1 += acc[nt][2] * ad_a + acc[nt][3] * ad_b;
    }
#pragma unroll
    for (int off = 1; off <= 2; off <<= 1) {
        ps0 += __shfl_xor_sync(0xffffffffu, ps0, off);
        pd0 += __shfl_xor_sync(0xffffffffu, pd0, off);
        ps1 += __shfl_xor_sync(0xffffffffu, ps1, off);
        pd1 += __shfl_xor_sync(0xffffffffu, pd1, off);
    }
    if ((t & 3) == 0) {
        if (r0 < N) {
            g_asrc[(size_t)r0 * 4 + quarter] = ps0;
            g_adst[(size_t)r0 * 4 + quarter] = pd0;
        }
        if (r1 < N) {
            g_asrc[(size_t)r1 * 4 + quarter] = ps1;
            g_adst[(size_t)r1 * 4 + quarter] = pd1;
        }
    }
}

// ---------------- K3: in-degree histogram over dst (2 edges/thread) ----------------
__global__ void k_hist(const int* __restrict__ ei, int E, int N) {
    int t = blockIdx.x * blockDim.x + threadIdx.x;
    int e = t * 2;
    if (e + 1 < E) {
        int2 d2 = __ldg((const int2*)(ei + E + e));
        atomicAdd(&g_cnt[clampN(d2.x, N)], 1);
        atomicAdd(&g_cnt[clampN(d2.y, N)], 1);
    } else if (e < E) {
        atomicAdd(&g_cnt[clampN(__ldg(ei + E + e), N)], 1);
    }
}

// ---------------- K4a/b/c: exclusive scan (+ self-loop slots) ----------------
__global__ void k_scan1(int n) {
    __shared__ int sh[512];
    int i = blockIdx.x * 512 + threadIdx.x;
    sh[threadIdx.x] = (i < n) ? g_cnt[i] : 0;
    __syncthreads();
    for (int off = 256; off > 0; off >>= 1) {
        if (threadIdx.x < off) sh[threadIdx.x] += sh[threadIdx.x + off];
        __syncthreads();
    }
    if (threadIdx.x == 0) g_blocksums[blockIdx.x] = sh[0];
}

__global__ void k_scan2(int nb) {
    __shared__ int sh[128];
    int t = threadIdx.x;
    int v = (t < nb) ? g_blocksums[t] : 0;
    sh[t] = v;
    __syncthreads();
    for (int off = 1; off < 128; off <<= 1) {
        int tmp = (t >= off) ? sh[t - off] : 0;
        __syncthreads();
        sh[t] += tmp;
        __syncthreads();
    }
    if (t < nb) g_blocksums[t] = sh[t] - v;    // exclusive
}

__global__ void k_scan3(int n) {               // +i adds self-loop slots
    __shared__ int sh[512];
    int i = blockIdx.x * 512 + threadIdx.x;
    int v = (i < n) ? g_cnt[i] : 0;
    sh[threadIdx.x] = v;
    __syncthreads();
    for (int off = 1; off < 512; off <<= 1) {
        int tmp = (threadIdx.x >= off) ? sh[threadIdx.x - off] : 0;
        __syncthreads();
        sh[threadIdx.x] += tmp;
        __syncthreads();
    }
    int excl = sh[threadIdx.x] - v + g_blocksums[blockIdx.x] + i;
    if (i < n) { g_rowstart[i] = excl; g_cursor[i] = excl; }
    if (i == n - 1) g_rowstart[n] = excl + v + 1;
}

// ---------------- K5: fill CSR columns (4 edges/thread + self-loops) ----------------
__global__ void k_fill(const int* __restrict__ ei, int E, int TE, int N) {
    int t = blockIdx.x * blockDim.x + threadIdx.x;
    int e = t * 4;
    if (e + 3 < E) {
        int4 s4 = __ldg((const int4*)(ei + e));
        int4 d4 = __ldg((const int4*)(ei + E + e));
        g_col[atomicAdd(&g_cursor[clampN(d4.x, N)], 1)] = clampN(s4.x, N);
        g_col[atomicAdd(&g_cursor[clampN(d4.y, N)], 1)] = clampN(s4.y, N);
        g_col[atomicAdd(&g_cursor[clampN(d4.z, N)], 1)] = clampN(s4.z, N);
        g_col[atomicAdd(&g_cursor[clampN(d4.w, N)], 1)] = clampN(s4.w, N);
    } else {
        for (; e < E; e++) {
            int s = clampN(__ldg(ei + e), N);
            int d = clampN(__ldg(ei + E + e), N);
            g_col[atomicAdd(&g_cursor[d], 1)] = s;
        }
    }
    if (t < N) g_col[atomicAdd(&g_cursor[t], 1)] = t;   // self-loops
}

// ---------------- K6: single-pass gather-aggregate, 4-edge MLP ----------------
__global__ __launch_bounds__(256) void k_aggregate(const float* __restrict__ bias,
                                                   float* __restrict__ out, int N) {
    int warp = (int)((blockIdx.x * (unsigned)blockDim.x + threadIdx.x) >> 5);
    if (warp >= N) return;
    int lane = threadIdx.x & 31;
    int head = lane >> 3;

    int start = g_rowstart[warp];
    int end   = g_rowstart[warp + 1];
    float adst_h = __ldg(&g_adst[(size_t)warp * 4 + head]);

    float den = 0.f;
    float acc[8];
#pragma unroll
    for (int j = 0; j < 8; j++) acc[j] = 0.f;
    const int cbase = lane * 8;

    int i = start;
    for (; i + 3 < end; i += 4) {
        int s0 = __ldg(&g_col[i]);
        int s1 = __ldg(&g_col[i + 1]);
        int s2 = __ldg(&g_col[i + 2]);
        int s3 = __ldg(&g_col[i + 3]);
        uint4 hv0 = *(const uint4*)(g_h16 + (size_t)s0 * HC + cbase);
        uint4 hv1 = *(const uint4*)(g_h16 + (size_t)s1 * HC + cbase);
        uint4 hv2 = *(const uint4*)(g_h16 + (size_t)s2 * HC + cbase);
        uint4 hv3 = *(const uint4*)(g_h16 + (size_t)s3 * HC + cbase);
        float a0 = __ldg(&g_asrc[(size_t)s0 * 4 + head]);
        float a1 = __ldg(&g_asrc[(size_t)s1 * 4 + head]);
        float a2 = __ldg(&g_asrc[(size_t)s2 * 4 + head]);
        float a3 = __ldg(&g_asrc[(size_t)s3 * 4 + head]);
        float w0 = __expf(lrelu(a0 + adst_h));
        float w1 = __expf(lrelu(a1 + adst_h));
        float w2 = __expf(lrelu(a2 + adst_h));
        float w3 = __expf(lrelu(a3 + adst_h));
        den += (w0 + w1) + (w2 + w3);
        float2 f;
        f = __half22float2(*(__half2*)&hv0.x); acc[0] += w0 * f.x; acc[1] += w0 * f.y;
        f = __half22float2(*(__half2*)&hv0.y); acc[2] += w0 * f.x; acc[3] += w0 * f.y;
        f = __half22float2(*(__half2*)&hv0.z); acc[4] += w0 * f.x; acc[5] += w0 * f.y;
        f = __half22float2(*(__half2*)&hv0.w); acc[6] += w0 * f.x; acc[7] += w0 * f.y;
        f = __half22float2(*(__half2*)&hv1.x); acc[0] += w1 * f.x; acc[1] += w1 * f.y;
        f = __half22float2(*(__half2*)&hv1.y); acc[2] += w1 * f.x; acc[3] += w1 * f.y;
        f = __half22float2(*(__half2*)&hv1.z); acc[4] += w1 * f.x; acc[5] += w1 * f.y;
        f = __half22float2(*(__half2*)&hv1.w); acc[6] += w1 * f.x; acc[7] += w1 * f.y;
        f = __half22float2(*(__half2*)&hv2.x); acc[0] += w2 * f.x; acc[1] += w2 * f.y;
        f = __half22float2(*(__half2*)&hv2.y); acc[2] += w2 * f.x; acc[3] += w2 * f.y;
        f = __half22float2(*(__half2*)&hv2.z); acc[4] += w2 * f.x; acc[5] += w2 * f.y;
        f = __half22float2(*(__half2*)&hv2.w); acc[6] += w2 * f.x; acc[7] += w2 * f.y;
        f = __half22float2(*(__half2*)&hv3.x); acc[0] += w3 * f.x; acc[1] += w3 * f.y;
        f = __half22float2(*(__half2*)&hv3.y); acc[2] += w3 * f.x; acc[3] += w3 * f.y;
        f = __half22float2(*(__half2*)&hv3.z); acc[4] += w3 * f.x; acc[5] += w3 * f.y;
        f = __half22float2(*(__half2*)&hv3.w); acc[6] += w3 * f.x; acc[7] += w3 * f.y;
    }
    for (; i < end; i++) {
        int s0 = __ldg(&g_col[i]);
        uint4 hv0 = *(const uint4*)(g_h16 + (size_t)s0 * HC + cbase);
        float a0 = __ldg(&g_asrc[(size_t)s0 * 4 + head]);
        float w0 = __expf(lrelu(a0 + adst_h));
        den += w0;
        float2 f;
        f = __half22float2(*(__half2*)&hv0.x); acc[0] += w0 * f.x; acc[1] += w0 * f.y;
        f = __half22float2(*(__half2*)&hv0.y); acc[2] += w0 * f.x; acc[3] += w0 * f.y;
        f = __half22float2(*(__half2*)&hv0.z); acc[4] += w0 * f.x; acc[5] += w0 * f.y;
        f = __half22float2(*(__half2*)&hv0.w); acc[6] += w0 * f.x; acc[7] += w0 * f.y;
    }

    float inv_den = 1.0f / (den + 1e-16f);
    const float4* bp = (const float4*)(bias + cbase);
    float4 b0 = __ldg(bp), b1 = __ldg(bp + 1);
    float4 o0 = {acc[0] * inv_den + b0.x, acc[1] * inv_den + b0.y,
                 acc[2] * inv_den + b0.z, acc[3] * inv_den + b0.w};
    float4 o1 = {acc[4] * inv_den + b1.x, acc[5] * inv_den + b1.y,
                 acc[6] * inv_den + b1.z, acc[7] * inv_den + b1.w};
    float4* op = (float4*)(out + (size_t)warp * HC + cbase);
    op[0] = o0;
    op[1] = o1;
}

// ---------------- launch ----------------
extern "C" void kernel_launch(void* const* d_in, const int* in_sizes, int n_in,
                              void* d_out, int out_size) {
    const float* x       = (const float*)d_in[0];
    const int*   ei      = (const int*)d_in[1];     // int32
    const float* W       = (const float*)d_in[2];
    const float* att_src = (const float*)d_in[3];
    const float* att_dst = (const float*)d_in[4];
    const float* bias    = (const float*)d_in[5];
    float*       out     = (float*)d_out;

    const int N   = in_sizes[0] / IN_CH;   // 50000
    const int E   = in_sizes[1] / 2;       // 800000
    const int TE  = E + N;                 // 850000
    const int RTn = (N + 15) / 16;         // 3125
    const int NB512 = (N + 511) / 512;     // 98
    const int E4 = (E + 3) / 4;
    const int E2 = (E + 1) / 2;

    k_split_x<<<(RTn * 256 + 255) / 256, 256>>>(x, N, RTn);
    k_split_w<<<(N + 255) / 256, 256>>>(W, N);   // also zeroes g_cnt
    k_mma<<<(RTn + 1) / 2, 256>>>(att_src, att_dst, N, RTn);
    k_hist<<<(E2 + 255) / 256, 256>>>(ei, E, N);
    k_scan1<<<NB512, 512>>>(N);
    k_scan2<<<1, 128>>>(NB512);
    k_scan3<<<NB512, 512>>>(N);
    int fill_threads = (E4 > N ? E4 : N);
    k_fill<<<(fill_threads + 255) / 256, 256>>>(ei, E, TE, N);
    long long agg_threads = (long long)N * 32;
    k_aggregate<<<(unsigned)((agg_threads + 255) / 256), 256>>>(bias, out, N);
}